// round 15
// baseline (speedup 1.0000x reference)
#include <cuda_runtime.h>
#include <cuda_fp16.h>
#include <math.h>

#define BB 4
#define NN 2048
#define MM 2048
#define QD 512
#define CD 64
#define NH 8
#define HD 64
#define INNER 512
#define GATE_HID 32

// Scratch (allocation-free rule: __device__ globals)
__device__ __half g_xh[BB * NN * QD];
__device__ __half g_gctxh[BB * MM * CD];
__device__ __half g_Wqt[INNER * QD];
__device__ __half g_Wkt[INNER * CD];
__device__ __half g_Wvt[INNER * CD];
__device__ __half g_Wot[QD * INNER];
__device__ __half g_Qh[BB * NN * INNER];
__device__ __half g_Kh[BB * MM * INNER];
__device__ __half g_Vt[BB * NH * HD * MM];
__device__ __half g_Ah[BB * NN * INNER];

// ---------------------------------------------------------------------------
// helpers
// ---------------------------------------------------------------------------
__device__ __forceinline__ unsigned pack_h2(float lo, float hi) {
    unsigned d;
    asm("cvt.rn.f16x2.f32 %0, %1, %2;" : "=r"(d) : "f"(hi), "f"(lo));
    return d;
}

__device__ __forceinline__ unsigned h2ex2(unsigned x) {
    unsigned y;
    asm("ex2.approx.f16x2 %0, %1;" : "=r"(y) : "r"(x));
    return y;
}

// f32-accumulator mma
__device__ __forceinline__ void mma_f16(float c[4], const unsigned a[4],
                                        unsigned b0, unsigned b1) {
    asm volatile(
        "mma.sync.aligned.m16n8k16.row.col.f32.f16.f16.f32 "
        "{%0,%1,%2,%3}, {%4,%5,%6,%7}, {%8,%9}, {%0,%1,%2,%3};"
        : "+f"(c[0]), "+f"(c[1]), "+f"(c[2]), "+f"(c[3])
        : "r"(a[0]), "r"(a[1]), "r"(a[2]), "r"(a[3]), "r"(b0), "r"(b1));
}

// f16-accumulator mma (C-frag: 2 f16x2 regs; layout == PV A-frag rows)
__device__ __forceinline__ void mma_f16h(unsigned c[2], const unsigned a[4],
                                         unsigned b0, unsigned b1) {
    asm volatile(
        "mma.sync.aligned.m16n8k16.row.col.f16.f16.f16.f16 "
        "{%0,%1}, {%2,%3,%4,%5}, {%6,%7}, {%0,%1};"
        : "+r"(c[0]), "+r"(c[1])
        : "r"(a[0]), "r"(a[1]), "r"(a[2]), "r"(a[3]), "r"(b0), "r"(b1));
}

#define CP16(dst, src) \
    asm volatile("cp.async.cg.shared.global [%0], [%1], 16;\n" \
                 :: "r"(dst), "l"(src))
#define CP_COMMIT() asm volatile("cp.async.commit_group;\n")
#define CP_WAIT1()  asm volatile("cp.async.wait_group 1;\n" ::: "memory")
#define CP_WAIT0()  asm volatile("cp.async.wait_group 0;\n" ::: "memory")

// ---------------------------------------------------------------------------
// Kernel 0: fused prep (round-14 proven, unchanged)
// ---------------------------------------------------------------------------
#define WC_BLK   1024
#define F2H_BLK  4096
#define GATE_BLK 1024

__global__ __launch_bounds__(256) void prep(
    const float* __restrict__ x, const float* __restrict__ ctx,
    const float* __restrict__ Wq, const float* __restrict__ Wk,
    const float* __restrict__ Wv, const float* __restrict__ Wo,
    const float* __restrict__ W1, const float* __restrict__ b1,
    const float* __restrict__ W2, const float* __restrict__ b2,
    __half* __restrict__ xh, __half* __restrict__ gctx,
    __half* __restrict__ Wqt, __half* __restrict__ Wkt,
    __half* __restrict__ Wvt, __half* __restrict__ Wot) {
    __shared__ float smbuf[2624];
    const int bid = blockIdx.x;
    const int tid = threadIdx.x;

    if (bid < WC_BLK) {
        const int z = bid >> 8;
        const int rem = bid & 255;
        const int by = rem >> 4, bx = rem & 15;
        const float* src = (z == 0) ? Wq : (z == 1) ? Wk : (z == 2) ? Wv : Wo;
        __half* dst = (z == 0) ? Wqt : (z == 1) ? Wkt : (z == 2) ? Wvt : Wot;
        const int R = (z == 1 || z == 2) ? CD : 512;
        const float scl = (z == 0) ? 0.125f * 1.44269504f : 1.0f;
        const int r0 = by * 32, c0 = bx * 32;
        if (r0 >= R) return;
        float (*t)[33] = (float(*)[33])smbuf;
        const int tx = tid & 31, ty = tid >> 5;
#pragma unroll
        for (int i = 0; i < 32; i += 8)
            t[ty + i][tx] = src[(size_t)(r0 + ty + i) * INNER + c0 + tx];
        __syncthreads();
#pragma unroll
        for (int i = 0; i < 32; i += 8)
            dst[(size_t)(c0 + ty + i) * R + r0 + tx] =
                __float2half(t[tx][ty + i] * scl);
    } else if (bid < WC_BLK + F2H_BLK) {
        const int i = (bid - WC_BLK) * 256 + tid;
        float4 v = ((const float4*)x)[i];
        uint2 u = make_uint2(pack_h2(v.x, v.y), pack_h2(v.z, v.w));
        ((uint2*)xh)[i] = u;
    } else {
        float* W1s = smbuf;
        float* W2s = smbuf + 2048;
        float* b1s = smbuf + 2080;
        float (*cs)[CD] = (float(*)[CD])(smbuf + 2112);

        for (int i = tid; i < CD * GATE_HID; i += 256) W1s[i] = W1[i];
        if (tid < GATE_HID) { W2s[tid] = W2[tid]; b1s[tid] = b1[tid]; }
        __syncthreads();

        const int warp = tid >> 5, lane = tid & 31;
        const int row = (bid - WC_BLK - F2H_BLK) * 8 + warp;
        const float* c = ctx + (size_t)row * CD;
        cs[warp][lane]      = c[lane];
        cs[warp][lane + 32] = c[lane + 32];
        __syncwarp();

        float h = b1s[lane];
#pragma unroll
        for (int i = 0; i < CD; i++)
            h = fmaf(cs[warp][i], W1s[i * GATE_HID + lane], h);
        h = fmaxf(h, 0.0f);
        float part = h * W2s[lane];
#pragma unroll
        for (int off = 16; off; off >>= 1)
            part += __shfl_xor_sync(0xffffffffu, part, off);
        const float g = 1.0f / (1.0f + __expf(-(part + b2[0])));

        __half* dst = gctx + (size_t)row * CD;
        dst[lane]      = __float2half(cs[warp][lane] * g);
        dst[lane + 32] = __float2half(cs[warp][lane + 32] * g);
    }
}

// ---------------------------------------------------------------------------
// GEMM core (round-12 proven, unchanged)
// ---------------------------------------------------------------------------
#define HS 20
#define TS 136
#define GEMM_SMEM (2 * 3 * 128 * HS * 4)

__device__ __forceinline__ void gemm_core(
    const __half* __restrict__ A, const __half* __restrict__ Bt,
    int K, unsigned* sm, float acc[2][8][4]) {
    const int tid = threadIdx.x;
    const int bm = blockIdx.y * 128, bn = blockIdx.x * 128;
    const int lane = tid & 31, wid = tid >> 5;
    const int gid = lane >> 2, tig = lane & 3;
    const int wm = (wid & 3) * 32, wn = (wid >> 2) * 64;

    unsigned* As = sm;
    unsigned* Bs = sm + 3 * 128 * HS;
    const int arow = tid >> 1, apart = tid & 1;
    const unsigned a_base = (unsigned)__cvta_generic_to_shared(As);
    const unsigned b_base = (unsigned)__cvta_generic_to_shared(Bs);
    const __half* ag = A + (size_t)(bm + arow) * K + apart * 16;
    const __half* bg = Bt + (size_t)(bn + arow) * K + apart * 16;
    const unsigned soff = (unsigned)((arow * HS + apart * 8) * 4);

    const int NS = K >> 5;

    CP16(a_base + soff, ag); CP16(a_base + soff + 16, ag + 8);
    CP16(b_base + soff, bg); CP16(b_base + soff + 16, bg + 8);
    CP_COMMIT();
    if (NS > 1) {
        const unsigned o1 = 128 * HS * 4;
        CP16(a_base + o1 + soff, ag + 32); CP16(a_base + o1 + soff + 16, ag + 40);
        CP16(b_base + o1 + soff, bg + 32); CP16(b_base + o1 + soff + 16, bg + 40);
    }
    CP_COMMIT();

    int buf = 0;
    for (int s = 0; s < NS; s++) {
        CP_WAIT1();
        __syncthreads();

        int nb = buf + 2; if (nb >= 3) nb -= 3;
        if (s + 2 < NS) {
            const unsigned on = (unsigned)(nb * 128 * HS * 4);
            const int k0 = (s + 2) * 32;
            CP16(a_base + on + soff, ag + k0);
            CP16(a_base + on + soff + 16, ag + k0 + 8);
            CP16(b_base + on + soff, bg + k0);
            CP16(b_base + on + soff + 16, bg + k0 + 8);
        }
        CP_COMMIT();

        unsigned* Ap = As + buf * 128 * HS;
        unsigned* Bp = Bs + buf * 128 * HS;
#pragma unroll
        for (int kc = 0; kc < 2; kc++) {
            unsigned a[2][4];
#pragma unroll
            for (int mt = 0; mt < 2; mt++) {
                const int r = wm + mt * 16 + gid;
                a[mt][0] = Ap[r * HS + kc * 8 + tig];
                a[mt][1] = Ap[(r + 8) * HS + kc * 8 + tig];
                a[mt][2] = Ap[r * HS + kc * 8 + 4 + tig];
                a[mt][3] = Ap[(r + 8) * HS + kc * 8 + 4 + tig];
            }
#pragma unroll
            for (int nt = 0; nt < 8; nt++) {
                const unsigned b0 = Bp[(wn + nt * 8 + gid) * HS + kc * 8 + tig];
                const unsigned b1 = Bp[(wn + nt * 8 + gid) * HS + kc * 8 + 4 + tig];
                mma_f16(acc[0][nt], a[0], b0, b1);
                mma_f16(acc[1][nt], a[1], b0, b1);
            }
        }
        buf++; if (buf == 3) buf = 0;
    }
}

// ---------------------------------------------------------------------------
// Kernel 2a: merged projections (round-12 proven, unchanged)
// ---------------------------------------------------------------------------
__global__ __launch_bounds__(256, 2) void proj3(
    const __half* __restrict__ xh, const __half* __restrict__ gctxh,
    const __half* __restrict__ Wqt, const __half* __restrict__ Wkt,
    const __half* __restrict__ Wvt,
    __half* __restrict__ Qh, __half* __restrict__ Kh, __half* __restrict__ Vt) {
    extern __shared__ unsigned sm[];
    const int z = blockIdx.z;
    const __half* A  = (z == 0) ? xh : gctxh;
    const __half* Bt = (z == 0) ? Wqt : ((z == 1) ? Wkt : Wvt);
    const int K = (z == 0) ? QD : CD;
    const int N = INNER;

    float acc[2][8][4];
#pragma unroll
    for (int mt = 0; mt < 2; mt++)
#pragma unroll
        for (int nt = 0; nt < 8; nt++)
#pragma unroll
            for (int j = 0; j < 4; j++) acc[mt][nt][j] = 0.0f;

    gemm_core(A, Bt, K, sm, acc);

    const int tid = threadIdx.x;
    const int bm = blockIdx.y * 128, bn = blockIdx.x * 128;
    const int lane = tid & 31, wid = tid >> 5;
    const int gid = lane >> 2, tig = lane & 3;
    const int wm = (wid & 3) * 32, wn = (wid >> 2) * 64;

    if (z < 2) {
        unsigned* Cw = (unsigned*)((z == 0) ? Qh : Kh);
        const int nw = N >> 1;
#pragma unroll
        for (int mt = 0; mt < 2; mt++) {
            const int r = bm + wm + mt * 16 + gid;
#pragma unroll
            for (int nt = 0; nt < 8; nt++) {
                const int c = bn + wn + nt * 8 + tig * 2;
                Cw[(size_t)r * nw + (c >> 1)] =
                    pack_h2(acc[mt][nt][0], acc[mt][nt][1]);
                Cw[(size_t)(r + 8) * nw + (c >> 1)] =
                    pack_h2(acc[mt][nt][2], acc[mt][nt][3]);
            }
        }
    } else {
        __syncthreads();
        __half* T = (__half*)sm;
#pragma unroll
        for (int mt = 0; mt < 2; mt++) {
            const int r = wm + mt * 16 + gid;
#pragma unroll
            for (int nt = 0; nt < 8; nt++) {
                const int c = wn + nt * 8 + tig * 2;
                T[c * TS + r]           = __float2half(acc[mt][nt][0]);
                T[(c + 1) * TS + r]     = __float2half(acc[mt][nt][1]);
                T[c * TS + r + 8]       = __float2half(acc[mt][nt][2]);
                T[(c + 1) * TS + r + 8] = __float2half(acc[mt][nt][3]);
            }
        }
        __syncthreads();
        const int c = tid >> 1, part = tid & 1;
        const int Cg = bn + c;
        const int hh = Cg >> 6, d = Cg & 63;
        const int bb = bm >> 11;
        const int tok0 = (bm & 2047) + part * 64;
        __half* dst = Vt + (((size_t)bb * NH + hh) * HD + d) * MM + tok0;
        const __half* srcT = T + c * TS + part * 64;
#pragma unroll
        for (int k = 0; k < 8; k++)
            *(uint4*)(dst + k * 8) = *(const uint4*)(srcT + k * 8);
    }
}

// ---------------------------------------------------------------------------
// Kernel 2b: output projection (round-12 proven, unchanged)
// ---------------------------------------------------------------------------
__global__ __launch_bounds__(256, 2) void hgemm_out(
    const __half* __restrict__ A, const __half* __restrict__ Bt,
    const float* __restrict__ bias, float* __restrict__ C, int N, int K) {
    extern __shared__ unsigned sm[];
    float acc[2][8][4];
#pragma unroll
    for (int mt = 0; mt < 2; mt++)
#pragma unroll
        for (int nt = 0; nt < 8; nt++)
#pragma unroll
            for (int j = 0; j < 4; j++) acc[mt][nt][j] = 0.0f;

    gemm_core(A, Bt, K, sm, acc);

    const int tid = threadIdx.x;
    const int bm = blockIdx.y * 128, bn = blockIdx.x * 128;
    const int lane = tid & 31, wid = tid >> 5;
    const int gid = lane >> 2, tig = lane & 3;
    const int wm = (wid & 3) * 32, wn = (wid >> 2) * 64;

#pragma unroll
    for (int mt = 0; mt < 2; mt++) {
        const int r = bm + wm + mt * 16 + gid;
#pragma unroll
        for (int nt = 0; nt < 8; nt++) {
            const int c = bn + wn + nt * 8 + tig * 2;
            const float b0 = bias[c], b1 = bias[c + 1];
            *(float2*)&C[(size_t)r * N + c] =
                make_float2(acc[mt][nt][0] + b0, acc[mt][nt][1] + b1);
            *(float2*)&C[(size_t)(r + 8) * N + c] =
                make_float2(acc[mt][nt][2] + b0, acc[mt][nt][3] + b1);
        }
    }
}

// ---------------------------------------------------------------------------
// Kernel 3: flash attention, REGISTER-SLIM for 2 CTAs/SM:
//  - S accumulated in f16 (mma f16.f16.f16.f16): 32 regs, and its C-frag
//    after in-place ex2.approx.f16x2 IS the PV A-frag (no packing, no ap).
//  - row sums l via ones-matrix mma chained over kk (exact f32; no shfl).
//  - Q frags reloaded per kk (transient), K/V staged via cp.async
//    double-buffer (no prefetch registers).
// 256q CTA, 8 warps, 32q x 64k warp tile, max-free base-2 softmax, f16 out.
// ---------------------------------------------------------------------------
#define KW 36
#define ONE2 0x3C003C00u  // f16x2 {1.0, 1.0}

__global__ __launch_bounds__(256, 2) void flash_f16(
    const __half* __restrict__ Q, const __half* __restrict__ K,
    const __half* __restrict__ V, __half* __restrict__ O) {
    extern __shared__ unsigned sh[];
    unsigned* Qs = sh;                  // [256][KW]
    unsigned* Ks = Qs + 256 * KW;       // [2][64][KW]
    unsigned* Vs = Ks + 2 * 64 * KW;    // [2][64][KW]

    const int b = blockIdx.z, h = blockIdx.y, q0 = blockIdx.x * 256;
    const int tid = threadIdx.x, w = tid >> 5, lane = tid & 31;
    const int gid = lane >> 2, tig = lane & 3;
    const int wr = w * 32;

    const __half* Qb = Q + ((size_t)b * NN + q0) * INNER + h * HD;
    const __half* Kb = K + (size_t)b * MM * INNER + h * HD;
    const __half* Vb = V + ((size_t)b * NH + h) * HD * MM;  // [d][M]

    // Stage Q tile (256 rows x 64 f16)
#pragma unroll
    for (int i = 0; i < 8; i++) {
        int f = tid + i * 256;
        int row = f >> 3, g = f & 7;
        uint4 v = *(const uint4*)(Qb + (size_t)row * INNER + g * 8);
        *(uint4*)&Qs[row * KW + g * 4] = v;
    }

    // cp.async staging coords (2 x 16B per thread per K and V tile)
    const int crow = tid >> 3;           // 0..31
    const int cg8 = (tid & 7) * 8;       // half offset within 64-half row
    const unsigned ksm = (unsigned)__cvta_generic_to_shared(
        &Ks[crow * KW + (cg8 >> 1)]);
    const unsigned vsm = (unsigned)__cvta_generic_to_shared(
        &Vs[crow * KW + (cg8 >> 1)]);
    const __half* kg = Kb + (size_t)crow * INNER + cg8;
    const __half* vg = Vb + (size_t)crow * MM + cg8;

    // Issue K/V tile 0 into buffer 0
    CP16(ksm, kg);
    CP16(ksm + 32 * KW * 4, kg + 32 * INNER);
    CP16(vsm, vg);
    CP16(vsm + 32 * KW * 4, vg + 32 * MM);
    CP_COMMIT();

    float o[2][8][4];
#pragma unroll
    for (int mt = 0; mt < 2; mt++)
#pragma unroll
        for (int nt = 0; nt < 8; nt++)
#pragma unroll
            for (int j = 0; j < 4; j++) o[mt][nt][j] = 0.0f;
    float lacc[2][4];
#pragma unroll
    for (int mt = 0; mt < 2; mt++)
#pragma unroll
        for (int j = 0; j < 4; j++) lacc[mt][j] = 0.0f;

    __syncthreads();  // Q visible

    for (int t = 0; t < MM; t += 64) {
        const int p = (t >> 6) & 1;
        const int po = p * 64 * KW;

        CP_WAIT0();
        __syncthreads();  // tile t visible; buf p^1 readers (tile t-1) done

        // Issue tile t+1 into buffer p^1
        if (t + 64 < MM) {
            const unsigned no = (unsigned)((p ^ 1) * 64 * KW * 4);
            const __half* kg1 = kg + (size_t)(t + 64) * INNER;
            const __half* vg1 = vg + (t + 64);
            CP16(ksm + no, kg1);
            CP16(ksm + no + 32 * KW * 4, kg1 + 32 * INNER);
            CP16(vsm + no, vg1);
            CP16(vsm + no + 32 * KW * 4, vg1 + 32 * MM);
            CP_COMMIT();
        }

        // S = Q @ K^T in f16 accumulators (s16[mt][nt] = {row r, row r+8})
        unsigned s16[2][8][2];
#pragma unroll
        for (int mt = 0; mt < 2; mt++)
#pragma unroll
            for (int nt = 0; nt < 8; nt++) {
                s16[mt][nt][0] = 0u;
                s16[mt][nt][1] = 0u;
            }
#pragma unroll
        for (int kk = 0; kk < 4; kk++) {
            unsigned qf[2][4];
#pragma unroll
            for (int mt = 0; mt < 2; mt++) {
                const int r = wr + mt * 16 + gid;
                qf[mt][0] = Qs[r * KW + kk * 8 + tig];
                qf[mt][1] = Qs[(r + 8) * KW + kk * 8 + tig];
                qf[mt][2] = Qs[r * KW + kk * 8 + tig + 4];
                qf[mt][3] = Qs[(r + 8) * KW + kk * 8 + tig + 4];
            }
#pragma unroll
            for (int nt = 0; nt < 8; nt++) {
                unsigned b0 = Ks[po + (nt * 8 + gid) * KW + kk * 8 + tig];
                unsigned b1 = Ks[po + (nt * 8 + gid) * KW + kk * 8 + tig + 4];
                mma_f16h(s16[0][nt], qf[0], b0, b1);
                mma_f16h(s16[1][nt], qf[1], b0, b1);
            }
        }

        // P = 2^S in place (f16x2) — C-frag becomes the PV A-frag directly
#pragma unroll
        for (int mt = 0; mt < 2; mt++)
#pragma unroll
            for (int nt = 0; nt < 8; nt++) {
                s16[mt][nt][0] = h2ex2(s16[mt][nt][0]);
                s16[mt][nt][1] = h2ex2(s16[mt][nt][1]);
            }

        // O += P @ V and l += P @ ones (both chained over kk)
#pragma unroll
        for (int kk = 0; kk < 4; kk++) {
            unsigned a0[4] = {s16[0][2 * kk][0], s16[0][2 * kk][1],
                              s16[0][2 * kk + 1][0], s16[0][2 * kk + 1][1]};
            unsigned a1[4] = {s16[1][2 * kk][0], s16[1][2 * kk][1],
                              s16[1][2 * kk + 1][0], s16[1][2 * kk + 1][1]};
            mma_f16(lacc[0], a0, ONE2, ONE2);
            mma_f16(lacc[1], a1, ONE2, ONE2);
#pragma unroll
            for (int nt = 0; nt < 8; nt++) {
                unsigned b0 = Vs[po + (nt * 8 + gid) * KW + kk * 8 + tig];
                unsigned b1 = Vs[po + (nt * 8 + gid) * KW + kk * 8 + tig + 4];
                mma_f16(o[0][nt], a0, b0, b1);
                mma_f16(o[1][nt], a1, b0, b1);
            }
        }
    }

    // Epilogue: l already exact per-row in lacc (all lanes identical value)
    unsigned* Ow = (unsigned*)O + (((size_t)b * NN + q0) * INNER + h * HD) / 2;
#pragma unroll
    for (int mt = 0; mt < 2; mt++) {
        const float i0 = 1.0f / lacc[mt][0], i1 = 1.0f / lacc[mt][2];
        const int r0 = wr + mt * 16 + gid;
#pragma unroll
        for (int nt = 0; nt < 8; nt++) {
            const int cw = nt * 4 + tig;
            Ow[(size_t)r0 * 256 + cw] =
                pack_h2(o[mt][nt][0] * i0, o[mt][nt][1] * i0);
            Ow[(size_t)(r0 + 8) * 256 + cw] =
                pack_h2(o[mt][nt][2] * i1, o[mt][nt][3] * i1);
        }
    }
}

// ---------------------------------------------------------------------------
extern "C" void kernel_launch(void* const* d_in, const int* in_sizes, int n_in,
                              void* d_out, int out_size) {
    const float* x   = (const float*)d_in[0];
    const float* ctx = (const float*)d_in[1];
    const float* Wq  = (const float*)d_in[2];
    const float* Wk  = (const float*)d_in[3];
    const float* Wv  = (const float*)d_in[4];
    const float* W1  = (const float*)d_in[5];
    const float* b1  = (const float*)d_in[6];
    const float* W2  = (const float*)d_in[7];
    const float* b2  = (const float*)d_in[8];
    const float* Wo  = (const float*)d_in[9];
    const float* bo  = (const float*)d_in[10];
    float* out = (float*)d_out;

    __half *xh, *gctxh, *Wqt, *Wkt, *Wvt, *Wot, *Qh, *Kh, *Vt, *Ah;
    cudaGetSymbolAddress((void**)&xh, g_xh);
    cudaGetSymbolAddress((void**)&gctxh, g_gctxh);
    cudaGetSymbolAddress((void**)&Wqt, g_Wqt);
    cudaGetSymbolAddress((void**)&Wkt, g_Wkt);
    cudaGetSymbolAddress((void**)&Wvt, g_Wvt);
    cudaGetSymbolAddress((void**)&Wot, g_Wot);
    cudaGetSymbolAddress((void**)&Qh, g_Qh);
    cudaGetSymbolAddress((void**)&Kh, g_Kh);
    cudaGetSymbolAddress((void**)&Vt, g_Vt);
    cudaGetSymbolAddress((void**)&Ah, g_Ah);

    cudaFuncSetAttribute(proj3,
                         cudaFuncAttributeMaxDynamicSharedMemorySize, GEMM_SMEM);
    cudaFuncSetAttribute(hgemm_out,
                         cudaFuncAttributeMaxDynamicSharedMemorySize, GEMM_SMEM);
    const int flash_smem = (256 + 4 * 64) * KW * (int)sizeof(unsigned);  // 73728 B
    cudaFuncSetAttribute(flash_f16,
                         cudaFuncAttributeMaxDynamicSharedMemorySize, flash_smem);

    // 0+1) fused prep
    prep<<<WC_BLK + F2H_BLK + GATE_BLK, 256>>>(
        x, ctx, Wq, Wk, Wv, Wo, W1, b1, W2, b2,
        xh, gctxh, Wqt, Wkt, Wvt, Wot);

    // 2) projections
    proj3<<<dim3(INNER / 128, BB * NN / 128, 3), 256, GEMM_SMEM>>>(
        xh, gctxh, Wqt, Wkt, Wvt, Qh, Kh, Vt);

    // 3) attention (f16-S slim flash, 2 CTAs/SM)
    flash_f16<<<dim3(NN / 256, NH, BB), 256, flash_smem>>>(Qh, Kh, Vt, Ah);

    // 4) output projection + bias -> f32 d_out
    hgemm_out<<<dim3(QD / 128, BB * NN / 128), 256, GEMM_SMEM>>>(
        Ah, Wot, bo, out, QD, INNER);
}

// round 16
// speedup vs baseline: 1.0392x; 1.0392x over previous
#include <cuda_runtime.h>
#include <cuda_fp16.h>
#include <math.h>

#define BB 4
#define NN 2048
#define MM 2048
#define QD 512
#define CD 64
#define NH 8
#define HD 64
#define INNER 512
#define GATE_HID 32

// Scratch (allocation-free rule: __device__ globals)
__device__ __half g_xh[BB * NN * QD];
__device__ __half g_gctxh[BB * MM * CD];
__device__ __half g_Wqt[INNER * QD];
__device__ __half g_Wkt[INNER * CD];
__device__ __half g_Wvt[INNER * CD];
__device__ __half g_Wot[QD * INNER];
__device__ __half g_Qh[BB * NN * INNER];
__device__ __half g_Kh[BB * MM * INNER];
__device__ __half g_Vt[BB * NH * HD * MM];
__device__ __half g_Ah[BB * NN * INNER];

// ---------------------------------------------------------------------------
// helpers
// ---------------------------------------------------------------------------
__device__ __forceinline__ unsigned pack_h2(float lo, float hi) {
    unsigned d;
    asm("cvt.rn.f16x2.f32 %0, %1, %2;" : "=r"(d) : "f"(hi), "f"(lo));
    return d;
}

__device__ __forceinline__ unsigned h2ex2(unsigned x) {
    unsigned y;
    asm("ex2.approx.f16x2 %0, %1;" : "=r"(y) : "r"(x));
    return y;
}

// f32-accumulator mma
__device__ __forceinline__ void mma_f16(float c[4], const unsigned a[4],
                                        unsigned b0, unsigned b1) {
    asm volatile(
        "mma.sync.aligned.m16n8k16.row.col.f32.f16.f16.f32 "
        "{%0,%1,%2,%3}, {%4,%5,%6,%7}, {%8,%9}, {%0,%1,%2,%3};"
        : "+f"(c[0]), "+f"(c[1]), "+f"(c[2]), "+f"(c[3])
        : "r"(a[0]), "r"(a[1]), "r"(a[2]), "r"(a[3]), "r"(b0), "r"(b1));
}

// f16-accumulator mma (C-frag: 2 f16x2 regs; layout == PV A-frag rows)
__device__ __forceinline__ void mma_f16h(unsigned c[2], const unsigned a[4],
                                         unsigned b0, unsigned b1) {
    asm volatile(
        "mma.sync.aligned.m16n8k16.row.col.f16.f16.f16.f16 "
        "{%0,%1}, {%2,%3,%4,%5}, {%6,%7}, {%0,%1};"
        : "+r"(c[0]), "+r"(c[1])
        : "r"(a[0]), "r"(a[1]), "r"(a[2]), "r"(a[3]), "r"(b0), "r"(b1));
}

#define CP16(dst, src) \
    asm volatile("cp.async.cg.shared.global [%0], [%1], 16;\n" \
                 :: "r"(dst), "l"(src))
#define CP_COMMIT() asm volatile("cp.async.commit_group;\n")
#define CP_WAIT1()  asm volatile("cp.async.wait_group 1;\n" ::: "memory")

// ---------------------------------------------------------------------------
// Kernel 0: fused prep (round-14 proven, unchanged)
// ---------------------------------------------------------------------------
#define WC_BLK   1024
#define F2H_BLK  4096
#define GATE_BLK 1024

__global__ __launch_bounds__(256) void prep(
    const float* __restrict__ x, const float* __restrict__ ctx,
    const float* __restrict__ Wq, const float* __restrict__ Wk,
    const float* __restrict__ Wv, const float* __restrict__ Wo,
    const float* __restrict__ W1, const float* __restrict__ b1,
    const float* __restrict__ W2, const float* __restrict__ b2,
    __half* __restrict__ xh, __half* __restrict__ gctx,
    __half* __restrict__ Wqt, __half* __restrict__ Wkt,
    __half* __restrict__ Wvt, __half* __restrict__ Wot) {
    __shared__ float smbuf[2624];
    const int bid = blockIdx.x;
    const int tid = threadIdx.x;

    if (bid < WC_BLK) {
        const int z = bid >> 8;
        const int rem = bid & 255;
        const int by = rem >> 4, bx = rem & 15;
        const float* src = (z == 0) ? Wq : (z == 1) ? Wk : (z == 2) ? Wv : Wo;
        __half* dst = (z == 0) ? Wqt : (z == 1) ? Wkt : (z == 2) ? Wvt : Wot;
        const int R = (z == 1 || z == 2) ? CD : 512;
        const float scl = (z == 0) ? 0.125f * 1.44269504f : 1.0f;
        const int r0 = by * 32, c0 = bx * 32;
        if (r0 >= R) return;
        float (*t)[33] = (float(*)[33])smbuf;
        const int tx = tid & 31, ty = tid >> 5;
#pragma unroll
        for (int i = 0; i < 32; i += 8)
            t[ty + i][tx] = src[(size_t)(r0 + ty + i) * INNER + c0 + tx];
        __syncthreads();
#pragma unroll
        for (int i = 0; i < 32; i += 8)
            dst[(size_t)(c0 + ty + i) * R + r0 + tx] =
                __float2half(t[tx][ty + i] * scl);
    } else if (bid < WC_BLK + F2H_BLK) {
        const int i = (bid - WC_BLK) * 256 + tid;
        float4 v = ((const float4*)x)[i];
        uint2 u = make_uint2(pack_h2(v.x, v.y), pack_h2(v.z, v.w));
        ((uint2*)xh)[i] = u;
    } else {
        float* W1s = smbuf;
        float* W2s = smbuf + 2048;
        float* b1s = smbuf + 2080;
        float (*cs)[CD] = (float(*)[CD])(smbuf + 2112);

        for (int i = tid; i < CD * GATE_HID; i += 256) W1s[i] = W1[i];
        if (tid < GATE_HID) { W2s[tid] = W2[tid]; b1s[tid] = b1[tid]; }
        __syncthreads();

        const int warp = tid >> 5, lane = tid & 31;
        const int row = (bid - WC_BLK - F2H_BLK) * 8 + warp;
        const float* c = ctx + (size_t)row * CD;
        cs[warp][lane]      = c[lane];
        cs[warp][lane + 32] = c[lane + 32];
        __syncwarp();

        float h = b1s[lane];
#pragma unroll
        for (int i = 0; i < CD; i++)
            h = fmaf(cs[warp][i], W1s[i * GATE_HID + lane], h);
        h = fmaxf(h, 0.0f);
        float part = h * W2s[lane];
#pragma unroll
        for (int off = 16; off; off >>= 1)
            part += __shfl_xor_sync(0xffffffffu, part, off);
        const float g = 1.0f / (1.0f + __expf(-(part + b2[0])));

        __half* dst = gctx + (size_t)row * CD;
        dst[lane]      = __float2half(cs[warp][lane] * g);
        dst[lane + 32] = __float2half(cs[warp][lane + 32] * g);
    }
}

// ---------------------------------------------------------------------------
// GEMM core (round-12 proven, unchanged)
// ---------------------------------------------------------------------------
#define HS 20
#define TS 136
#define GEMM_SMEM (2 * 3 * 128 * HS * 4)

__device__ __forceinline__ void gemm_core(
    const __half* __restrict__ A, const __half* __restrict__ Bt,
    int K, unsigned* sm, float acc[2][8][4]) {
    const int tid = threadIdx.x;
    const int bm = blockIdx.y * 128, bn = blockIdx.x * 128;
    const int lane = tid & 31, wid = tid >> 5;
    const int gid = lane >> 2, tig = lane & 3;
    const int wm = (wid & 3) * 32, wn = (wid >> 2) * 64;

    unsigned* As = sm;
    unsigned* Bs = sm + 3 * 128 * HS;
    const int arow = tid >> 1, apart = tid & 1;
    const unsigned a_base = (unsigned)__cvta_generic_to_shared(As);
    const unsigned b_base = (unsigned)__cvta_generic_to_shared(Bs);
    const __half* ag = A + (size_t)(bm + arow) * K + apart * 16;
    const __half* bg = Bt + (size_t)(bn + arow) * K + apart * 16;
    const unsigned soff = (unsigned)((arow * HS + apart * 8) * 4);

    const int NS = K >> 5;

    CP16(a_base + soff, ag); CP16(a_base + soff + 16, ag + 8);
    CP16(b_base + soff, bg); CP16(b_base + soff + 16, bg + 8);
    CP_COMMIT();
    if (NS > 1) {
        const unsigned o1 = 128 * HS * 4;
        CP16(a_base + o1 + soff, ag + 32); CP16(a_base + o1 + soff + 16, ag + 40);
        CP16(b_base + o1 + soff, bg + 32); CP16(b_base + o1 + soff + 16, bg + 40);
    }
    CP_COMMIT();

    int buf = 0;
    for (int s = 0; s < NS; s++) {
        CP_WAIT1();
        __syncthreads();

        int nb = buf + 2; if (nb >= 3) nb -= 3;
        if (s + 2 < NS) {
            const unsigned on = (unsigned)(nb * 128 * HS * 4);
            const int k0 = (s + 2) * 32;
            CP16(a_base + on + soff, ag + k0);
            CP16(a_base + on + soff + 16, ag + k0 + 8);
            CP16(b_base + on + soff, bg + k0);
            CP16(b_base + on + soff + 16, bg + k0 + 8);
        }
        CP_COMMIT();

        unsigned* Ap = As + buf * 128 * HS;
        unsigned* Bp = Bs + buf * 128 * HS;
#pragma unroll
        for (int kc = 0; kc < 2; kc++) {
            unsigned a[2][4];
#pragma unroll
            for (int mt = 0; mt < 2; mt++) {
                const int r = wm + mt * 16 + gid;
                a[mt][0] = Ap[r * HS + kc * 8 + tig];
                a[mt][1] = Ap[(r + 8) * HS + kc * 8 + tig];
                a[mt][2] = Ap[r * HS + kc * 8 + 4 + tig];
                a[mt][3] = Ap[(r + 8) * HS + kc * 8 + 4 + tig];
            }
#pragma unroll
            for (int nt = 0; nt < 8; nt++) {
                const unsigned b0 = Bp[(wn + nt * 8 + gid) * HS + kc * 8 + tig];
                const unsigned b1 = Bp[(wn + nt * 8 + gid) * HS + kc * 8 + 4 + tig];
                mma_f16(acc[0][nt], a[0], b0, b1);
                mma_f16(acc[1][nt], a[1], b0, b1);
            }
        }
        buf++; if (buf == 3) buf = 0;
    }
}

// ---------------------------------------------------------------------------
// Kernel 2a: merged projections (round-12 proven, unchanged)
// ---------------------------------------------------------------------------
__global__ __launch_bounds__(256, 2) void proj3(
    const __half* __restrict__ xh, const __half* __restrict__ gctxh,
    const __half* __restrict__ Wqt, const __half* __restrict__ Wkt,
    const __half* __restrict__ Wvt,
    __half* __restrict__ Qh, __half* __restrict__ Kh, __half* __restrict__ Vt) {
    extern __shared__ unsigned sm[];
    const int z = blockIdx.z;
    const __half* A  = (z == 0) ? xh : gctxh;
    const __half* Bt = (z == 0) ? Wqt : ((z == 1) ? Wkt : Wvt);
    const int K = (z == 0) ? QD : CD;
    const int N = INNER;

    float acc[2][8][4];
#pragma unroll
    for (int mt = 0; mt < 2; mt++)
#pragma unroll
        for (int nt = 0; nt < 8; nt++)
#pragma unroll
            for (int j = 0; j < 4; j++) acc[mt][nt][j] = 0.0f;

    gemm_core(A, Bt, K, sm, acc);

    const int tid = threadIdx.x;
    const int bm = blockIdx.y * 128, bn = blockIdx.x * 128;
    const int lane = tid & 31, wid = tid >> 5;
    const int gid = lane >> 2, tig = lane & 3;
    const int wm = (wid & 3) * 32, wn = (wid >> 2) * 64;

    if (z < 2) {
        unsigned* Cw = (unsigned*)((z == 0) ? Qh : Kh);
        const int nw = N >> 1;
#pragma unroll
        for (int mt = 0; mt < 2; mt++) {
            const int r = bm + wm + mt * 16 + gid;
#pragma unroll
            for (int nt = 0; nt < 8; nt++) {
                const int c = bn + wn + nt * 8 + tig * 2;
                Cw[(size_t)r * nw + (c >> 1)] =
                    pack_h2(acc[mt][nt][0], acc[mt][nt][1]);
                Cw[(size_t)(r + 8) * nw + (c >> 1)] =
                    pack_h2(acc[mt][nt][2], acc[mt][nt][3]);
            }
        }
    } else {
        __syncthreads();
        __half* T = (__half*)sm;
#pragma unroll
        for (int mt = 0; mt < 2; mt++) {
            const int r = wm + mt * 16 + gid;
#pragma unroll
            for (int nt = 0; nt < 8; nt++) {
                const int c = wn + nt * 8 + tig * 2;
                T[c * TS + r]           = __float2half(acc[mt][nt][0]);
                T[(c + 1) * TS + r]     = __float2half(acc[mt][nt][1]);
                T[c * TS + r + 8]       = __float2half(acc[mt][nt][2]);
                T[(c + 1) * TS + r + 8] = __float2half(acc[mt][nt][3]);
            }
        }
        __syncthreads();
        const int c = tid >> 1, part = tid & 1;
        const int Cg = bn + c;
        const int hh = Cg >> 6, d = Cg & 63;
        const int bb = bm >> 11;
        const int tok0 = (bm & 2047) + part * 64;
        __half* dst = Vt + (((size_t)bb * NH + hh) * HD + d) * MM + tok0;
        const __half* srcT = T + c * TS + part * 64;
#pragma unroll
        for (int k = 0; k < 8; k++)
            *(uint4*)(dst + k * 8) = *(const uint4*)(srcT + k * 8);
    }
}

// ---------------------------------------------------------------------------
// Kernel 2b: output projection (round-12 proven, unchanged)
// ---------------------------------------------------------------------------
__global__ __launch_bounds__(256, 2) void hgemm_out(
    const __half* __restrict__ A, const __half* __restrict__ Bt,
    const float* __restrict__ bias, float* __restrict__ C, int N, int K) {
    extern __shared__ unsigned sm[];
    float acc[2][8][4];
#pragma unroll
    for (int mt = 0; mt < 2; mt++)
#pragma unroll
        for (int nt = 0; nt < 8; nt++)
#pragma unroll
            for (int j = 0; j < 4; j++) acc[mt][nt][j] = 0.0f;

    gemm_core(A, Bt, K, sm, acc);

    const int tid = threadIdx.x;
    const int bm = blockIdx.y * 128, bn = blockIdx.x * 128;
    const int lane = tid & 31, wid = tid >> 5;
    const int gid = lane >> 2, tig = lane & 3;
    const int wm = (wid & 3) * 32, wn = (wid >> 2) * 64;

#pragma unroll
    for (int mt = 0; mt < 2; mt++) {
        const int r = bm + wm + mt * 16 + gid;
#pragma unroll
        for (int nt = 0; nt < 8; nt++) {
            const int c = bn + wn + nt * 8 + tig * 2;
            const float b0 = bias[c], b1 = bias[c + 1];
            *(float2*)&C[(size_t)r * N + c] =
                make_float2(acc[mt][nt][0] + b0, acc[mt][nt][1] + b1);
            *(float2*)&C[(size_t)(r + 8) * N + c] =
                make_float2(acc[mt][nt][2] + b0, acc[mt][nt][3] + b1);
        }
    }
}

// ---------------------------------------------------------------------------
// Kernel 3: flash attention HYBRID: round-12 proven shell (register-prefetch
// double buffer, hoisted Q frags, 1 barrier/tile, launch_bounds(256,1))
// + f16-S machinery (S in f16 accumulators; in-place ex2.approx.f16x2 turns
// the S C-frag into the PV A-frag with zero packing; row sums via ones-mma;
// shfl-free epilogue). MUFU work halves, 32 cvt/tile removed.
// ---------------------------------------------------------------------------
#define KW 36
#define ONE2 0x3C003C00u  // f16x2 {1.0, 1.0}

__global__ __launch_bounds__(256, 1) void flash_f16(
    const __half* __restrict__ Q, const __half* __restrict__ K,
    const __half* __restrict__ V, __half* __restrict__ O) {
    extern __shared__ unsigned sh[];
    unsigned* Qs = sh;                  // [256][KW]
    unsigned* Ks = Qs + 256 * KW;       // [2][64][KW]
    unsigned* Vs = Ks + 2 * 64 * KW;    // [2][64][KW]

    const int b = blockIdx.z, h = blockIdx.y, q0 = blockIdx.x * 256;
    const int tid = threadIdx.x, w = tid >> 5, lane = tid & 31;
    const int gid = lane >> 2, tig = lane & 3;
    const int wr = w * 32;

    const __half* Qb = Q + ((size_t)b * NN + q0) * INNER + h * HD;
    const __half* Kb = K + (size_t)b * MM * INNER + h * HD;
    const __half* Vb = V + ((size_t)b * NH + h) * HD * MM;  // [d][M]

    // Stage Q tile (256 rows x 64 f16)
#pragma unroll
    for (int i = 0; i < 8; i++) {
        int f = tid + i * 256;
        int row = f >> 3, g = f & 7;
        uint4 v = *(const uint4*)(Qb + (size_t)row * INNER + g * 8);
        *(uint4*)&Qs[row * KW + g * 4] = v;
    }

    // Prefetch K/V tile 0 (registers)
    uint4 pk[2], pv[2];
#pragma unroll
    for (int i = 0; i < 2; i++) {
        int f = tid + i * 256;
        int row = f >> 3, g = f & 7;
        pk[i] = *(const uint4*)(Kb + (size_t)row * INNER + g * 8);
        pv[i] = *(const uint4*)(Vb + (size_t)row * MM + g * 8);
    }
    __syncthreads();

    // Hoist Q fragments
    unsigned qf[4][2][4];
#pragma unroll
    for (int kk = 0; kk < 4; kk++)
#pragma unroll
        for (int mt = 0; mt < 2; mt++) {
            int r = wr + mt * 16 + gid;
            qf[kk][mt][0] = Qs[r * KW + kk * 8 + tig];
            qf[kk][mt][1] = Qs[(r + 8) * KW + kk * 8 + tig];
            qf[kk][mt][2] = Qs[r * KW + kk * 8 + tig + 4];
            qf[kk][mt][3] = Qs[(r + 8) * KW + kk * 8 + tig + 4];
        }

    float o[2][8][4];
#pragma unroll
    for (int mt = 0; mt < 2; mt++)
#pragma unroll
        for (int nt = 0; nt < 8; nt++)
#pragma unroll
            for (int j = 0; j < 4; j++) o[mt][nt][j] = 0.0f;
    float lacc[2][4];
#pragma unroll
    for (int mt = 0; mt < 2; mt++)
#pragma unroll
        for (int j = 0; j < 4; j++) lacc[mt][j] = 0.0f;

    const int srow = tid >> 3, sg = (tid & 7) * 4;

    for (int t = 0; t < MM; t += 64) {
        const int p = (t >> 6) & 1;
        unsigned* Kp = Ks + p * 64 * KW;
        unsigned* Vp = Vs + p * 64 * KW;

        // Store prefetched tile
#pragma unroll
        for (int i = 0; i < 2; i++) {
            int row = srow + i * 32;
            *(uint4*)&Kp[row * KW + sg] = pk[i];
            *(uint4*)&Vp[row * KW + sg] = pv[i];
        }
        __syncthreads();

        // Prefetch next tile (latency overlapped with compute)
        if (t + 64 < MM) {
#pragma unroll
            for (int i = 0; i < 2; i++) {
                int row = srow + i * 32;
                pk[i] = *(const uint4*)(Kb + (size_t)(t + 64 + row) * INNER + sg * 2);
                pv[i] = *(const uint4*)(Vb + (size_t)row * MM + t + 64 + sg * 2);
            }
        }

        // S = Q @ K^T in f16 accumulators
        unsigned s16[2][8][2];
#pragma unroll
        for (int mt = 0; mt < 2; mt++)
#pragma unroll
            for (int nt = 0; nt < 8; nt++) {
                s16[mt][nt][0] = 0u;
                s16[mt][nt][1] = 0u;
            }
#pragma unroll
        for (int kk = 0; kk < 4; kk++) {
#pragma unroll
            for (int nt = 0; nt < 8; nt++) {
                unsigned b0 = Kp[(nt * 8 + gid) * KW + kk * 8 + tig];
                unsigned b1 = Kp[(nt * 8 + gid) * KW + kk * 8 + tig + 4];
                mma_f16h(s16[0][nt], qf[kk][0], b0, b1);
                mma_f16h(s16[1][nt], qf[kk][1], b0, b1);
            }
        }

        // P = 2^S in place (f16x2) — S C-frag becomes the PV A-frag
#pragma unroll
        for (int mt = 0; mt < 2; mt++)
#pragma unroll
            for (int nt = 0; nt < 8; nt++) {
                s16[mt][nt][0] = h2ex2(s16[mt][nt][0]);
                s16[mt][nt][1] = h2ex2(s16[mt][nt][1]);
            }

        // O += P @ V and l += P @ ones
#pragma unroll
        for (int kk = 0; kk < 4; kk++) {
            unsigned a0[4] = {s16[0][2 * kk][0], s16[0][2 * kk][1],
                              s16[0][2 * kk + 1][0], s16[0][2 * kk + 1][1]};
            unsigned a1[4] = {s16[1][2 * kk][0], s16[1][2 * kk][1],
                              s16[1][2 * kk + 1][0], s16[1][2 * kk + 1][1]};
            mma_f16(lacc[0], a0, ONE2, ONE2);
            mma_f16(lacc[1], a1, ONE2, ONE2);
#pragma unroll
            for (int nt = 0; nt < 8; nt++) {
                unsigned b0 = Vp[(nt * 8 + gid) * KW + kk * 8 + tig];
                unsigned b1 = Vp[(nt * 8 + gid) * KW + kk * 8 + tig + 4];
                mma_f16(o[0][nt], a0, b0, b1);
                mma_f16(o[1][nt], a1, b0, b1);
            }
        }
    }

    // Epilogue: lacc holds exact row sums (no shfl needed)
    unsigned* Ow = (unsigned*)O + (((size_t)b * NN + q0) * INNER + h * HD) / 2;
#pragma unroll
    for (int mt = 0; mt < 2; mt++) {
        const float i0 = 1.0f / lacc[mt][0], i1 = 1.0f / lacc[mt][2];
        const int r0 = wr + mt * 16 + gid;
#pragma unroll
        for (int nt = 0; nt < 8; nt++) {
            const int cw = nt * 4 + tig;
            Ow[(size_t)r0 * 256 + cw] =
                pack_h2(o[mt][nt][0] * i0, o[mt][nt][1] * i0);
            Ow[(size_t)(r0 + 8) * 256 + cw] =
                pack_h2(o[mt][nt][2] * i1, o[mt][nt][3] * i1);
        }
    }
}

// ---------------------------------------------------------------------------
extern "C" void kernel_launch(void* const* d_in, const int* in_sizes, int n_in,
                              void* d_out, int out_size) {
    const float* x   = (const float*)d_in[0];
    const float* ctx = (const float*)d_in[1];
    const float* Wq  = (const float*)d_in[2];
    const float* Wk  = (const float*)d_in[3];
    const float* Wv  = (const float*)d_in[4];
    const float* W1  = (const float*)d_in[5];
    const float* b1  = (const float*)d_in[6];
    const float* W2  = (const float*)d_in[7];
    const float* b2  = (const float*)d_in[8];
    const float* Wo  = (const float*)d_in[9];
    const float* bo  = (const float*)d_in[10];
    float* out = (float*)d_out;

    __half *xh, *gctxh, *Wqt, *Wkt, *Wvt, *Wot, *Qh, *Kh, *Vt, *Ah;
    cudaGetSymbolAddress((void**)&xh, g_xh);
    cudaGetSymbolAddress((void**)&gctxh, g_gctxh);
    cudaGetSymbolAddress((void**)&Wqt, g_Wqt);
    cudaGetSymbolAddress((void**)&Wkt, g_Wkt);
    cudaGetSymbolAddress((void**)&Wvt, g_Wvt);
    cudaGetSymbolAddress((void**)&Wot, g_Wot);
    cudaGetSymbolAddress((void**)&Qh, g_Qh);
    cudaGetSymbolAddress((void**)&Kh, g_Kh);
    cudaGetSymbolAddress((void**)&Vt, g_Vt);
    cudaGetSymbolAddress((void**)&Ah, g_Ah);

    cudaFuncSetAttribute(proj3,
                         cudaFuncAttributeMaxDynamicSharedMemorySize, GEMM_SMEM);
    cudaFuncSetAttribute(hgemm_out,
                         cudaFuncAttributeMaxDynamicSharedMemorySize, GEMM_SMEM);
    const int flash_smem = (256 + 4 * 64) * KW * (int)sizeof(unsigned);  // 73728 B
    cudaFuncSetAttribute(flash_f16,
                         cudaFuncAttributeMaxDynamicSharedMemorySize, flash_smem);

    // 0+1) fused prep
    prep<<<WC_BLK + F2H_BLK + GATE_BLK, 256>>>(
        x, ctx, Wq, Wk, Wv, Wo, W1, b1, W2, b2,
        xh, gctxh, Wqt, Wkt, Wvt, Wot);

    // 2) projections
    proj3<<<dim3(INNER / 128, BB * NN / 128, 3), 256, GEMM_SMEM>>>(
        xh, gctxh, Wqt, Wkt, Wvt, Qh, Kh, Vt);

    // 3) attention (hybrid f16-S flash in the round-12 shell)
    flash_f16<<<dim3(NN / 256, NH, BB), 256, flash_smem>>>(Qh, Kh, Vt, Ah);

    // 4) output projection + bias -> f32 d_out
    hgemm_out<<<dim3(QD / 128, BB * NN / 128), 256, GEMM_SMEM>>>(
        Ah, Wot, bo, out, QD, INNER);
}

// round 17
// speedup vs baseline: 1.0667x; 1.0264x over previous
#include <cuda_runtime.h>
#include <cuda_fp16.h>
#include <math.h>

#define BB 4
#define NN 2048
#define MM 2048
#define QD 512
#define CD 64
#define NH 8
#define HD 64
#define INNER 512
#define GATE_HID 32

// Scratch (allocation-free rule: __device__ globals)
__device__ __half g_xh[BB * NN * QD];
__device__ __half g_gctxh[BB * MM * CD];
__device__ __half g_Wqt[INNER * QD];
__device__ __half g_Wkt[INNER * CD];
__device__ __half g_Wvt[INNER * CD];
__device__ __half g_Wot[QD * INNER];
__device__ __half g_Qh[BB * NN * INNER];
__device__ __half g_Kh[BB * MM * INNER];
__device__ __half g_Vt[BB * NH * HD * MM];
__device__ __half g_Ah[BB * NN * INNER];

// ---------------------------------------------------------------------------
// helpers
// ---------------------------------------------------------------------------
__device__ __forceinline__ unsigned pack_h2(float lo, float hi) {
    unsigned d;
    asm("cvt.rn.f16x2.f32 %0, %1, %2;" : "=r"(d) : "f"(hi), "f"(lo));
    return d;
}

__device__ __forceinline__ unsigned h2ex2(unsigned x) {
    unsigned y;
    asm("ex2.approx.f16x2 %0, %1;" : "=r"(y) : "r"(x));
    return y;
}

// f32-accumulator mma
__device__ __forceinline__ void mma_f16(float c[4], const unsigned a[4],
                                        unsigned b0, unsigned b1) {
    asm volatile(
        "mma.sync.aligned.m16n8k16.row.col.f32.f16.f16.f32 "
        "{%0,%1,%2,%3}, {%4,%5,%6,%7}, {%8,%9}, {%0,%1,%2,%3};"
        : "+f"(c[0]), "+f"(c[1]), "+f"(c[2]), "+f"(c[3])
        : "r"(a[0]), "r"(a[1]), "r"(a[2]), "r"(a[3]), "r"(b0), "r"(b1));
}

// f16-accumulator mma (C-frag: 2 f16x2 regs; layout == PV A-frag rows)
__device__ __forceinline__ void mma_f16h(unsigned c[2], const unsigned a[4],
                                         unsigned b0, unsigned b1) {
    asm volatile(
        "mma.sync.aligned.m16n8k16.row.col.f16.f16.f16.f16 "
        "{%0,%1}, {%2,%3,%4,%5}, {%6,%7}, {%0,%1};"
        : "+r"(c[0]), "+r"(c[1])
        : "r"(a[0]), "r"(a[1]), "r"(a[2]), "r"(a[3]), "r"(b0), "r"(b1));
}

// ldmatrix x4 (four 8x8 f16 tiles; reg i <- lane-group i addresses)
__device__ __forceinline__ void ldsm4(unsigned r[4], unsigned addr) {
    asm volatile(
        "ldmatrix.sync.aligned.m8n8.x4.shared.b16 {%0,%1,%2,%3}, [%4];"
        : "=r"(r[0]), "=r"(r[1]), "=r"(r[2]), "=r"(r[3]) : "r"(addr));
}

#define CP16(dst, src) \
    asm volatile("cp.async.cg.shared.global [%0], [%1], 16;\n" \
                 :: "r"(dst), "l"(src))
#define CP_COMMIT() asm volatile("cp.async.commit_group;\n")
#define CP_WAIT1()  asm volatile("cp.async.wait_group 1;\n" ::: "memory")

// ---------------------------------------------------------------------------
// Kernel 0: fused prep (round-14 proven, unchanged)
// ---------------------------------------------------------------------------
#define WC_BLK   1024
#define F2H_BLK  4096
#define GATE_BLK 1024

__global__ __launch_bounds__(256) void prep(
    const float* __restrict__ x, const float* __restrict__ ctx,
    const float* __restrict__ Wq, const float* __restrict__ Wk,
    const float* __restrict__ Wv, const float* __restrict__ Wo,
    const float* __restrict__ W1, const float* __restrict__ b1,
    const float* __restrict__ W2, const float* __restrict__ b2,
    __half* __restrict__ xh, __half* __restrict__ gctx,
    __half* __restrict__ Wqt, __half* __restrict__ Wkt,
    __half* __restrict__ Wvt, __half* __restrict__ Wot) {
    __shared__ float smbuf[2624];
    const int bid = blockIdx.x;
    const int tid = threadIdx.x;

    if (bid < WC_BLK) {
        const int z = bid >> 8;
        const int rem = bid & 255;
        const int by = rem >> 4, bx = rem & 15;
        const float* src = (z == 0) ? Wq : (z == 1) ? Wk : (z == 2) ? Wv : Wo;
        __half* dst = (z == 0) ? Wqt : (z == 1) ? Wkt : (z == 2) ? Wvt : Wot;
        const int R = (z == 1 || z == 2) ? CD : 512;
        const float scl = (z == 0) ? 0.125f * 1.44269504f : 1.0f;
        const int r0 = by * 32, c0 = bx * 32;
        if (r0 >= R) return;
        float (*t)[33] = (float(*)[33])smbuf;
        const int tx = tid & 31, ty = tid >> 5;
#pragma unroll
        for (int i = 0; i < 32; i += 8)
            t[ty + i][tx] = src[(size_t)(r0 + ty + i) * INNER + c0 + tx];
        __syncthreads();
#pragma unroll
        for (int i = 0; i < 32; i += 8)
            dst[(size_t)(c0 + ty + i) * R + r0 + tx] =
                __float2half(t[tx][ty + i] * scl);
    } else if (bid < WC_BLK + F2H_BLK) {
        const int i = (bid - WC_BLK) * 256 + tid;
        float4 v = ((const float4*)x)[i];
        uint2 u = make_uint2(pack_h2(v.x, v.y), pack_h2(v.z, v.w));
        ((uint2*)xh)[i] = u;
    } else {
        float* W1s = smbuf;
        float* W2s = smbuf + 2048;
        float* b1s = smbuf + 2080;
        float (*cs)[CD] = (float(*)[CD])(smbuf + 2112);

        for (int i = tid; i < CD * GATE_HID; i += 256) W1s[i] = W1[i];
        if (tid < GATE_HID) { W2s[tid] = W2[tid]; b1s[tid] = b1[tid]; }
        __syncthreads();

        const int warp = tid >> 5, lane = tid & 31;
        const int row = (bid - WC_BLK - F2H_BLK) * 8 + warp;
        const float* c = ctx + (size_t)row * CD;
        cs[warp][lane]      = c[lane];
        cs[warp][lane + 32] = c[lane + 32];
        __syncwarp();

        float h = b1s[lane];
#pragma unroll
        for (int i = 0; i < CD; i++)
            h = fmaf(cs[warp][i], W1s[i * GATE_HID + lane], h);
        h = fmaxf(h, 0.0f);
        float part = h * W2s[lane];
#pragma unroll
        for (int off = 16; off; off >>= 1)
            part += __shfl_xor_sync(0xffffffffu, part, off);
        const float g = 1.0f / (1.0f + __expf(-(part + b2[0])));

        __half* dst = gctx + (size_t)row * CD;
        dst[lane]      = __float2half(cs[warp][lane] * g);
        dst[lane + 32] = __float2half(cs[warp][lane + 32] * g);
    }
}

// ---------------------------------------------------------------------------
// GEMM core (round-12 proven, unchanged)
// ---------------------------------------------------------------------------
#define HS 20
#define TS 136
#define GEMM_SMEM (2 * 3 * 128 * HS * 4)

__device__ __forceinline__ void gemm_core(
    const __half* __restrict__ A, const __half* __restrict__ Bt,
    int K, unsigned* sm, float acc[2][8][4]) {
    const int tid = threadIdx.x;
    const int bm = blockIdx.y * 128, bn = blockIdx.x * 128;
    const int lane = tid & 31, wid = tid >> 5;
    const int gid = lane >> 2, tig = lane & 3;
    const int wm = (wid & 3) * 32, wn = (wid >> 2) * 64;

    unsigned* As = sm;
    unsigned* Bs = sm + 3 * 128 * HS;
    const int arow = tid >> 1, apart = tid & 1;
    const unsigned a_base = (unsigned)__cvta_generic_to_shared(As);
    const unsigned b_base = (unsigned)__cvta_generic_to_shared(Bs);
    const __half* ag = A + (size_t)(bm + arow) * K + apart * 16;
    const __half* bg = Bt + (size_t)(bn + arow) * K + apart * 16;
    const unsigned soff = (unsigned)((arow * HS + apart * 8) * 4);

    const int NS = K >> 5;

    CP16(a_base + soff, ag); CP16(a_base + soff + 16, ag + 8);
    CP16(b_base + soff, bg); CP16(b_base + soff + 16, bg + 8);
    CP_COMMIT();
    if (NS > 1) {
        const unsigned o1 = 128 * HS * 4;
        CP16(a_base + o1 + soff, ag + 32); CP16(a_base + o1 + soff + 16, ag + 40);
        CP16(b_base + o1 + soff, bg + 32); CP16(b_base + o1 + soff + 16, bg + 40);
    }
    CP_COMMIT();

    int buf = 0;
    for (int s = 0; s < NS; s++) {
        CP_WAIT1();
        __syncthreads();

        int nb = buf + 2; if (nb >= 3) nb -= 3;
        if (s + 2 < NS) {
            const unsigned on = (unsigned)(nb * 128 * HS * 4);
            const int k0 = (s + 2) * 32;
            CP16(a_base + on + soff, ag + k0);
            CP16(a_base + on + soff + 16, ag + k0 + 8);
            CP16(b_base + on + soff, bg + k0);
            CP16(b_base + on + soff + 16, bg + k0 + 8);
        }
        CP_COMMIT();

        unsigned* Ap = As + buf * 128 * HS;
        unsigned* Bp = Bs + buf * 128 * HS;
#pragma unroll
        for (int kc = 0; kc < 2; kc++) {
            unsigned a[2][4];
#pragma unroll
            for (int mt = 0; mt < 2; mt++) {
                const int r = wm + mt * 16 + gid;
                a[mt][0] = Ap[r * HS + kc * 8 + tig];
                a[mt][1] = Ap[(r + 8) * HS + kc * 8 + tig];
                a[mt][2] = Ap[r * HS + kc * 8 + 4 + tig];
                a[mt][3] = Ap[(r + 8) * HS + kc * 8 + 4 + tig];
            }
#pragma unroll
            for (int nt = 0; nt < 8; nt++) {
                const unsigned b0 = Bp[(wn + nt * 8 + gid) * HS + kc * 8 + tig];
                const unsigned b1 = Bp[(wn + nt * 8 + gid) * HS + kc * 8 + 4 + tig];
                mma_f16(acc[0][nt], a[0], b0, b1);
                mma_f16(acc[1][nt], a[1], b0, b1);
            }
        }
        buf++; if (buf == 3) buf = 0;
    }
}

// ---------------------------------------------------------------------------
// Kernel 2a: merged projections (round-12 proven, unchanged)
// ---------------------------------------------------------------------------
__global__ __launch_bounds__(256, 2) void proj3(
    const __half* __restrict__ xh, const __half* __restrict__ gctxh,
    const __half* __restrict__ Wqt, const __half* __restrict__ Wkt,
    const __half* __restrict__ Wvt,
    __half* __restrict__ Qh, __half* __restrict__ Kh, __half* __restrict__ Vt) {
    extern __shared__ unsigned sm[];
    const int z = blockIdx.z;
    const __half* A  = (z == 0) ? xh : gctxh;
    const __half* Bt = (z == 0) ? Wqt : ((z == 1) ? Wkt : Wvt);
    const int K = (z == 0) ? QD : CD;
    const int N = INNER;

    float acc[2][8][4];
#pragma unroll
    for (int mt = 0; mt < 2; mt++)
#pragma unroll
        for (int nt = 0; nt < 8; nt++)
#pragma unroll
            for (int j = 0; j < 4; j++) acc[mt][nt][j] = 0.0f;

    gemm_core(A, Bt, K, sm, acc);

    const int tid = threadIdx.x;
    const int bm = blockIdx.y * 128, bn = blockIdx.x * 128;
    const int lane = tid & 31, wid = tid >> 5;
    const int gid = lane >> 2, tig = lane & 3;
    const int wm = (wid & 3) * 32, wn = (wid >> 2) * 64;

    if (z < 2) {
        unsigned* Cw = (unsigned*)((z == 0) ? Qh : Kh);
        const int nw = N >> 1;
#pragma unroll
        for (int mt = 0; mt < 2; mt++) {
            const int r = bm + wm + mt * 16 + gid;
#pragma unroll
            for (int nt = 0; nt < 8; nt++) {
                const int c = bn + wn + nt * 8 + tig * 2;
                Cw[(size_t)r * nw + (c >> 1)] =
                    pack_h2(acc[mt][nt][0], acc[mt][nt][1]);
                Cw[(size_t)(r + 8) * nw + (c >> 1)] =
                    pack_h2(acc[mt][nt][2], acc[mt][nt][3]);
            }
        }
    } else {
        __syncthreads();
        __half* T = (__half*)sm;
#pragma unroll
        for (int mt = 0; mt < 2; mt++) {
            const int r = wm + mt * 16 + gid;
#pragma unroll
            for (int nt = 0; nt < 8; nt++) {
                const int c = wn + nt * 8 + tig * 2;
                T[c * TS + r]           = __float2half(acc[mt][nt][0]);
                T[(c + 1) * TS + r]     = __float2half(acc[mt][nt][1]);
                T[c * TS + r + 8]       = __float2half(acc[mt][nt][2]);
                T[(c + 1) * TS + r + 8] = __float2half(acc[mt][nt][3]);
            }
        }
        __syncthreads();
        const int c = tid >> 1, part = tid & 1;
        const int Cg = bn + c;
        const int hh = Cg >> 6, d = Cg & 63;
        const int bb = bm >> 11;
        const int tok0 = (bm & 2047) + part * 64;
        __half* dst = Vt + (((size_t)bb * NH + hh) * HD + d) * MM + tok0;
        const __half* srcT = T + c * TS + part * 64;
#pragma unroll
        for (int k = 0; k < 8; k++)
            *(uint4*)(dst + k * 8) = *(const uint4*)(srcT + k * 8);
    }
}

// ---------------------------------------------------------------------------
// Kernel 2b: output projection (round-12 proven, unchanged)
// ---------------------------------------------------------------------------
__global__ __launch_bounds__(256, 2) void hgemm_out(
    const __half* __restrict__ A, const __half* __restrict__ Bt,
    const float* __restrict__ bias, float* __restrict__ C, int N, int K) {
    extern __shared__ unsigned sm[];
    float acc[2][8][4];
#pragma unroll
    for (int mt = 0; mt < 2; mt++)
#pragma unroll
        for (int nt = 0; nt < 8; nt++)
#pragma unroll
            for (int j = 0; j < 4; j++) acc[mt][nt][j] = 0.0f;

    gemm_core(A, Bt, K, sm, acc);

    const int tid = threadIdx.x;
    const int bm = blockIdx.y * 128, bn = blockIdx.x * 128;
    const int lane = tid & 31, wid = tid >> 5;
    const int gid = lane >> 2, tig = lane & 3;
    const int wm = (wid & 3) * 32, wn = (wid >> 2) * 64;

#pragma unroll
    for (int mt = 0; mt < 2; mt++) {
        const int r = bm + wm + mt * 16 + gid;
#pragma unroll
        for (int nt = 0; nt < 8; nt++) {
            const int c = bn + wn + nt * 8 + tig * 2;
            const float b0 = bias[c], b1 = bias[c + 1];
            *(float2*)&C[(size_t)r * N + c] =
                make_float2(acc[mt][nt][0] + b0, acc[mt][nt][1] + b1);
            *(float2*)&C[(size_t)(r + 8) * N + c] =
                make_float2(acc[mt][nt][2] + b0, acc[mt][nt][3] + b1);
        }
    }
}

// ---------------------------------------------------------------------------
// Kernel 3: flash attention = round-16 hybrid + LDMATRIX fragment loads.
// All K/V b-fragments and Q a-fragments load via ldmatrix.x4: per warp per
// tile the shared-pipe issue count drops 128 LDS.32 -> 32 LDSM.x4 (plus the
// one-time Q hoist 32 -> 8). KW=36 stride keeps 8x16B ldmatrix rows
// conflict-free (banks 4i..4i+3 distinct).
// Shell: register-prefetch double buffer, 1 barrier/tile, lb(256,1).
// f16-S + in-place ex2.f16x2 + ones-mma row sums (round-16 proven).
// ---------------------------------------------------------------------------
#define KW 36
#define ONE2 0x3C003C00u  // f16x2 {1.0, 1.0}

__global__ __launch_bounds__(256, 1) void flash_f16(
    const __half* __restrict__ Q, const __half* __restrict__ K,
    const __half* __restrict__ V, __half* __restrict__ O) {
    extern __shared__ unsigned sh[];
    unsigned* Qs = sh;                  // [256][KW]
    unsigned* Ks = Qs + 256 * KW;       // [2][64][KW]
    unsigned* Vs = Ks + 2 * 64 * KW;    // [2][64][KW]

    const int b = blockIdx.z, h = blockIdx.y, q0 = blockIdx.x * 256;
    const int tid = threadIdx.x, w = tid >> 5, lane = tid & 31;
    const int gid = lane >> 2;
    const int wr = w * 32;

    const __half* Qb = Q + ((size_t)b * NN + q0) * INNER + h * HD;
    const __half* Kb = K + (size_t)b * MM * INNER + h * HD;
    const __half* Vb = V + ((size_t)b * NH + h) * HD * MM;  // [d][M]

    // Stage Q tile (256 rows x 64 f16)
#pragma unroll
    for (int i = 0; i < 8; i++) {
        int f = tid + i * 256;
        int row = f >> 3, g = f & 7;
        uint4 v = *(const uint4*)(Qb + (size_t)row * INNER + g * 8);
        *(uint4*)&Qs[row * KW + g * 4] = v;
    }

    // Prefetch K/V tile 0 (registers)
    uint4 pk[2], pv[2];
#pragma unroll
    for (int i = 0; i < 2; i++) {
        int f = tid + i * 256;
        int row = f >> 3, g = f & 7;
        pk[i] = *(const uint4*)(Kb + (size_t)row * INNER + g * 8);
        pv[i] = *(const uint4*)(Vb + (size_t)row * MM + g * 8);
    }
    __syncthreads();

    // ldmatrix per-lane base addresses
    const int l8 = lane & 7, sel = lane >> 3;
    // B/V frag (per nt-pair): lane groups -> {nt0 k0-7, nt0 k8-15, nt1 k0-7, nt1 k8-15}
    const unsigned bf = (unsigned)((((sel >> 1) * 8 + l8) * KW + (sel & 1) * 4) * 4);
    const unsigned ks_b = (unsigned)__cvta_generic_to_shared(Ks) + bf;
    const unsigned vs_b = (unsigned)__cvta_generic_to_shared(Vs) + bf;
    // Q a-frag: lane groups -> {r0-7 k0-7, r8-15 k0-7, r0-7 k8-15, r8-15 k8-15}
    const unsigned q_b = (unsigned)__cvta_generic_to_shared(Qs) +
        (unsigned)(((wr + (sel & 1) * 8 + l8) * KW + (sel >> 1) * 4) * 4);

    // Hoist Q fragments via ldmatrix (8 x LDSM.x4)
    unsigned qf[4][2][4];
#pragma unroll
    for (int kk = 0; kk < 4; kk++)
#pragma unroll
        for (int mt = 0; mt < 2; mt++)
            ldsm4(qf[kk][mt], q_b + (unsigned)((mt * 16 * KW + kk * 8) * 4));

    float o[2][8][4];
#pragma unroll
    for (int mt = 0; mt < 2; mt++)
#pragma unroll
        for (int nt = 0; nt < 8; nt++)
#pragma unroll
            for (int j = 0; j < 4; j++) o[mt][nt][j] = 0.0f;
    float lacc[2][4];
#pragma unroll
    for (int mt = 0; mt < 2; mt++)
#pragma unroll
        for (int j = 0; j < 4; j++) lacc[mt][j] = 0.0f;

    const int srow = tid >> 3, sg = (tid & 7) * 4;

    for (int t = 0; t < MM; t += 64) {
        const int p = (t >> 6) & 1;
        unsigned* Kp = Ks + p * 64 * KW;
        unsigned* Vp = Vs + p * 64 * KW;
        const unsigned pb = (unsigned)(p * 64 * KW * 4);

        // Store prefetched tile
#pragma unroll
        for (int i = 0; i < 2; i++) {
            int row = srow + i * 32;
            *(uint4*)&Kp[row * KW + sg] = pk[i];
            *(uint4*)&Vp[row * KW + sg] = pv[i];
        }
        __syncthreads();

        // Prefetch next tile (latency overlapped with compute)
        if (t + 64 < MM) {
#pragma unroll
            for (int i = 0; i < 2; i++) {
                int row = srow + i * 32;
                pk[i] = *(const uint4*)(Kb + (size_t)(t + 64 + row) * INNER + sg * 2);
                pv[i] = *(const uint4*)(Vb + (size_t)row * MM + t + 64 + sg * 2);
            }
        }

        // S = Q @ K^T in f16 accumulators (b-frags via ldmatrix.x4)
        unsigned s16[2][8][2];
#pragma unroll
        for (int mt = 0; mt < 2; mt++)
#pragma unroll
            for (int nt = 0; nt < 8; nt++) {
                s16[mt][nt][0] = 0u;
                s16[mt][nt][1] = 0u;
            }
#pragma unroll
        for (int kk = 0; kk < 4; kk++) {
#pragma unroll
            for (int ntp = 0; ntp < 4; ntp++) {
                unsigned bb[4];
                ldsm4(bb, ks_b + pb + (unsigned)((ntp * 16 * KW + kk * 8) * 4));
                mma_f16h(s16[0][2 * ntp],     qf[kk][0], bb[0], bb[1]);
                mma_f16h(s16[0][2 * ntp + 1], qf[kk][0], bb[2], bb[3]);
                mma_f16h(s16[1][2 * ntp],     qf[kk][1], bb[0], bb[1]);
                mma_f16h(s16[1][2 * ntp + 1], qf[kk][1], bb[2], bb[3]);
            }
        }

        // P = 2^S in place (f16x2) — S C-frag becomes the PV A-frag
#pragma unroll
        for (int mt = 0; mt < 2; mt++)
#pragma unroll
            for (int nt = 0; nt < 8; nt++) {
                s16[mt][nt][0] = h2ex2(s16[mt][nt][0]);
                s16[mt][nt][1] = h2ex2(s16[mt][nt][1]);
            }

        // O += P @ V and l += P @ ones (V b-frags via ldmatrix.x4)
#pragma unroll
        for (int kk = 0; kk < 4; kk++) {
            unsigned a0[4] = {s16[0][2 * kk][0], s16[0][2 * kk][1],
                              s16[0][2 * kk + 1][0], s16[0][2 * kk + 1][1]};
            unsigned a1[4] = {s16[1][2 * kk][0], s16[1][2 * kk][1],
                              s16[1][2 * kk + 1][0], s16[1][2 * kk + 1][1]};
            mma_f16(lacc[0], a0, ONE2, ONE2);
            mma_f16(lacc[1], a1, ONE2, ONE2);
#pragma unroll
            for (int ntp = 0; ntp < 4; ntp++) {
                unsigned bb[4];
                ldsm4(bb, vs_b + pb + (unsigned)((ntp * 16 * KW + kk * 8) * 4));
                mma_f16(o[0][2 * ntp],     a0, bb[0], bb[1]);
                mma_f16(o[0][2 * ntp + 1], a0, bb[2], bb[3]);
                mma_f16(o[1][2 * ntp],     a1, bb[0], bb[1]);
                mma_f16(o[1][2 * ntp + 1], a1, bb[2], bb[3]);
            }
        }
    }

    // Epilogue: lacc holds exact row sums (no shfl needed)
    const int tig = lane & 3;
    unsigned* Ow = (unsigned*)O + (((size_t)b * NN + q0) * INNER + h * HD) / 2;
#pragma unroll
    for (int mt = 0; mt < 2; mt++) {
        const float i0 = 1.0f / lacc[mt][0], i1 = 1.0f / lacc[mt][2];
        const int r0 = wr + mt * 16 + gid;
#pragma unroll
        for (int nt = 0; nt < 8; nt++) {
            const int cw = nt * 4 + tig;
            Ow[(size_t)r0 * 256 + cw] =
                pack_h2(o[mt][nt][0] * i0, o[mt][nt][1] * i0);
            Ow[(size_t)(r0 + 8) * 256 + cw] =
                pack_h2(o[mt][nt][2] * i1, o[mt][nt][3] * i1);
        }
    }
}

// ---------------------------------------------------------------------------
extern "C" void kernel_launch(void* const* d_in, const int* in_sizes, int n_in,
                              void* d_out, int out_size) {
    const float* x   = (const float*)d_in[0];
    const float* ctx = (const float*)d_in[1];
    const float* Wq  = (const float*)d_in[2];
    const float* Wk  = (const float*)d_in[3];
    const float* Wv  = (const float*)d_in[4];
    const float* W1  = (const float*)d_in[5];
    const float* b1  = (const float*)d_in[6];
    const float* W2  = (const float*)d_in[7];
    const float* b2  = (const float*)d_in[8];
    const float* Wo  = (const float*)d_in[9];
    const float* bo  = (const float*)d_in[10];
    float* out = (float*)d_out;

    __half *xh, *gctxh, *Wqt, *Wkt, *Wvt, *Wot, *Qh, *Kh, *Vt, *Ah;
    cudaGetSymbolAddress((void**)&xh, g_xh);
    cudaGetSymbolAddress((void**)&gctxh, g_gctxh);
    cudaGetSymbolAddress((void**)&Wqt, g_Wqt);
    cudaGetSymbolAddress((void**)&Wkt, g_Wkt);
    cudaGetSymbolAddress((void**)&Wvt, g_Wvt);
    cudaGetSymbolAddress((void**)&Wot, g_Wot);
    cudaGetSymbolAddress((void**)&Qh, g_Qh);
    cudaGetSymbolAddress((void**)&Kh, g_Kh);
    cudaGetSymbolAddress((void**)&Vt, g_Vt);
    cudaGetSymbolAddress((void**)&Ah, g_Ah);

    cudaFuncSetAttribute(proj3,
                         cudaFuncAttributeMaxDynamicSharedMemorySize, GEMM_SMEM);
    cudaFuncSetAttribute(hgemm_out,
                         cudaFuncAttributeMaxDynamicSharedMemorySize, GEMM_SMEM);
    const int flash_smem = (256 + 4 * 64) * KW * (int)sizeof(unsigned);  // 73728 B
    cudaFuncSetAttribute(flash_f16,
                         cudaFuncAttributeMaxDynamicSharedMemorySize, flash_smem);

    // 0+1) fused prep
    prep<<<WC_BLK + F2H_BLK + GATE_BLK, 256>>>(
        x, ctx, Wq, Wk, Wv, Wo, W1, b1, W2, b2,
        xh, gctxh, Wqt, Wkt, Wvt, Wot);

    // 2) projections
    proj3<<<dim3(INNER / 128, BB * NN / 128, 3), 256, GEMM_SMEM>>>(
        xh, gctxh, Wqt, Wkt, Wvt, Qh, Kh, Vt);

    // 3) attention (ldmatrix + f16-S flash)
    flash_f16<<<dim3(NN / 256, NH, BB), 256, flash_smem>>>(Qh, Kh, Vt, Ah);

    // 4) output projection + bias -> f32 d_out
    hgemm_out<<<dim3(QD / 128, BB * NN / 128), 256, GEMM_SMEM>>>(
        Ah, Wot, bo, out, QD, INNER);
}